// round 5
// baseline (speedup 1.0000x reference)
#include <cuda_runtime.h>

// ---------------------------------------------------------------------------
// QuantumRNNCell, two-kernel version:
//  K1 (qsim): 6-qubit statevector sim, 2 batch rows per warp (16 lanes/row,
//     4 complex amps per lane). Writes PauliZ expvals to padded scratch.
//  K2 (stream): barrier-free, smem-free streaming kernel. Per-thread fixed
//     column group; fc weights held in 28 registers. 4-row unrolled
//     grid-stride loop -> 12 loads in flight per warp continuously.
// ---------------------------------------------------------------------------

#define NQ 6
#define NLAYERS 3
#define HDIM 1024
#define QSTRIDE 8     // padded floats per row in scratch
#define MAXB 32768

__device__ float g_qexp[MAXB * QSTRIDE];   // 1 MB scratch (L2-resident)

// ---- in-register pair gates (complex pair at hi2 indices i0, i1) -----------
__device__ __forceinline__ void rx_pair(float a[8], int i0, int i1, float c, float s) {
    float re0 = a[2*i0], im0 = a[2*i0+1], re1 = a[2*i1], im1 = a[2*i1+1];
    a[2*i0]   = c*re0 + s*im1;
    a[2*i0+1] = c*im0 - s*re1;
    a[2*i1]   = c*re1 + s*im0;
    a[2*i1+1] = c*im1 - s*re0;
}
__device__ __forceinline__ void ry_pair(float a[8], int i0, int i1, float c, float s) {
    float re0 = a[2*i0], im0 = a[2*i0+1], re1 = a[2*i1], im1 = a[2*i1+1];
    a[2*i0]   = c*re0 - s*re1;
    a[2*i0+1] = c*im0 - s*im1;
    a[2*i1]   = s*re0 + c*re1;
    a[2*i1+1] = s*im0 + c*im1;
}
__device__ __forceinline__ void rz_one(float a[8], int i, float c, float sg) {
    float re = a[2*i], im = a[2*i+1];
    a[2*i]   = c*re - sg*im;
    a[2*i+1] = c*im + sg*re;
}

// ---- shuffle gates for wires 2..5 (mask m = 1<<(5-w) < 16) -----------------
__device__ __forceinline__ void rx_shfl(float a[8], int m, float c, float s) {
#pragma unroll
    for (int k = 0; k < 4; k++) {
        float orr = __shfl_xor_sync(0xFFFFFFFFu, a[2*k],   m);
        float oii = __shfl_xor_sync(0xFFFFFFFFu, a[2*k+1], m);
        a[2*k]   = c*a[2*k]   + s*oii;
        a[2*k+1] = c*a[2*k+1] - s*orr;
    }
}
__device__ __forceinline__ void ry_shfl(float a[8], int m, float c, float s, unsigned lane) {
    float sg = (lane & (unsigned)m) ? s : -s;
#pragma unroll
    for (int k = 0; k < 4; k++) {
        float orr = __shfl_xor_sync(0xFFFFFFFFu, a[2*k],   m);
        float oii = __shfl_xor_sync(0xFFFFFFFFu, a[2*k+1], m);
        a[2*k]   = c*a[2*k]   + sg*orr;
        a[2*k+1] = c*a[2*k+1] + sg*oii;
    }
}
__device__ __forceinline__ void rz_shfl(float a[8], int m, float c, float s, unsigned lane) {
    float sg = (lane & (unsigned)m) ? s : -s;
#pragma unroll
    for (int k = 0; k < 4; k++) rz_one(a, k, c, sg);
}

// ---- gate dispatch (w compile-time after unroll) ---------------------------
__device__ __forceinline__ void apply_rx(int w, float a[8], float c, float s, unsigned lane) {
    if (w == 0)      { rx_pair(a, 0, 2, c, s); rx_pair(a, 1, 3, c, s); }
    else if (w == 1) { rx_pair(a, 0, 1, c, s); rx_pair(a, 2, 3, c, s); }
    else             rx_shfl(a, 1 << (5 - w), c, s);
}
__device__ __forceinline__ void apply_ry(int w, float a[8], float c, float s, unsigned lane) {
    if (w == 0)      { ry_pair(a, 0, 2, c, s); ry_pair(a, 1, 3, c, s); }
    else if (w == 1) { ry_pair(a, 0, 1, c, s); ry_pair(a, 2, 3, c, s); }
    else             ry_shfl(a, 1 << (5 - w), c, s, lane);
}
__device__ __forceinline__ void apply_rz(int w, float a[8], float c, float s, unsigned lane) {
    if (w == 0) {
        rz_one(a, 0, c, -s); rz_one(a, 1, c, -s);
        rz_one(a, 2, c,  s); rz_one(a, 3, c,  s);
    } else if (w == 1) {
        rz_one(a, 0, c, -s); rz_one(a, 2, c, -s);
        rz_one(a, 1, c,  s); rz_one(a, 3, c,  s);
    } else rz_shfl(a, 1 << (5 - w), c, s, lane);
}

__device__ __forceinline__ void apply_cnot_ring(int q, float a[8], unsigned lane) {
    if (q == 0) {
        float t;
        t = a[4]; a[4] = a[6]; a[6] = t;
        t = a[5]; a[5] = a[7]; a[7] = t;
    } else if (q == 1) {
#pragma unroll
        for (int k = 1; k < 4; k += 2) {
            a[2*k]   = __shfl_xor_sync(0xFFFFFFFFu, a[2*k],   8);
            a[2*k+1] = __shfl_xor_sync(0xFFFFFFFFu, a[2*k+1], 8);
        }
    } else if (q == 5) {
        if (lane & 1u) {
            float t;
            t = a[0]; a[0] = a[4]; a[4] = t;
            t = a[1]; a[1] = a[5]; a[5] = t;
            t = a[2]; a[2] = a[6]; a[6] = t;
            t = a[3]; a[3] = a[7]; a[7] = t;
        }
    } else {
        int cb = 1 << (5 - q);
        int tm = 1 << (4 - q);
        bool ctrl = (lane & (unsigned)cb) != 0;
#pragma unroll
        for (int k = 0; k < 4; k++) {
            float vr = __shfl_xor_sync(0xFFFFFFFFu, a[2*k],   tm);
            float vi = __shfl_xor_sync(0xFFFFFFFFu, a[2*k+1], tm);
            if (ctrl) { a[2*k] = vr; a[2*k+1] = vi; }
        }
    }
}

// ---- kernel 1: sim, 16 rows per 256-thread block ---------------------------
__global__ __launch_bounds__(256)
void qsim_kernel(const float* __restrict__ x,
                 const float* __restrict__ qw,   // (3,6)
                 int B) {
    __shared__ float swc[NLAYERS * NQ];
    __shared__ float sws[NLAYERS * NQ];

    const int tid = threadIdx.x;
    const int warp = tid >> 5;
    const unsigned lane = tid & 31u;
    const unsigned lane16 = lane & 15u;
    const int half = (int)(lane >> 4);

    if (tid < NLAYERS * NQ) {
        float s, c;
        __sincosf(__ldg(&qw[tid]) * 0.5f, &s, &c);
        swc[tid] = c; sws[tid] = s;
    }
    __syncthreads();

    const int myrow = blockIdx.x * 16 + warp * 2 + half;
    const int b = min(myrow, B - 1);

    float xc[NQ], xs[NQ];
#pragma unroll
    for (int j = 0; j < NQ; j++) {
        __sincosf(__ldg(&x[b * NQ + j]) * 0.5f, &xs[j], &xc[j]);
    }

    float a[8];
#pragma unroll
    for (int k = 0; k < 8; k++) a[k] = 0.0f;
    a[0] = (lane16 == 0) ? 1.0f : 0.0f;

#pragma unroll
    for (int i = 0; i < NQ; i++) {
        int j1 = (i + 1) % NQ, j2 = (i + 2) % NQ;
        apply_rx(i, a, xc[i], xs[i], lane);
        apply_ry(i, a, xc[j1], xs[j1], lane);
        apply_rz(i, a, xc[j2], xs[j2], lane);
    }

#pragma unroll
    for (int l = 0; l < NLAYERS; l++) {
#pragma unroll
        for (int q = 0; q < NQ; q++)
            apply_ry(q, a, swc[l * NQ + q], sws[l * NQ + q], lane);
#pragma unroll
        for (int q = 0; q < NQ; q++) apply_cnot_ring(q, a, lane);
    }

    float p0 = a[0]*a[0] + a[1]*a[1];
    float p1 = a[2]*a[2] + a[3]*a[3];
    float p2 = a[4]*a[4] + a[5]*a[5];
    float p3 = a[6]*a[6] + a[7]*a[7];
    float ptot = p0 + p1 + p2 + p3;

    float e[NQ];
    e[0] = (p0 + p1) - (p2 + p3);   // wire0: state bit5 (hi2 bit1)
    e[1] = (p0 - p1) + (p2 - p3);   // wire1: state bit4 (hi2 bit0)
#pragma unroll
    for (int j = 2; j < NQ; j++) {
        float sg = (lane16 & (unsigned)(1 << (5 - j))) ? -1.0f : 1.0f;
        e[j] = sg * ptot;
    }
#pragma unroll
    for (int off = 8; off; off >>= 1) {
#pragma unroll
        for (int j = 0; j < NQ; j++)
            e[j] += __shfl_xor_sync(0xFFFFFFFFu, e[j], off);
    }
    if (lane16 == 0 && myrow < B) {
        float4* dst = (float4*)&g_qexp[myrow * QSTRIDE];
        dst[0] = make_float4(e[0], e[1], e[2], e[3]);
        dst[1] = make_float4(e[4], e[5], 0.0f, 0.0f);
    }
}

// ---- kernel 2: barrier-free smem-free stream -------------------------------
__global__ __launch_bounds__(256)
void stream_kernel(const float* __restrict__ hx,
                   const float* __restrict__ fc_w,  // (1024,6)
                   const float* __restrict__ fc_b,  // (1024,)
                   float* __restrict__ out,
                   int B) {
    const int tid = threadIdx.x;     // fixed column group: cols 4*tid..4*tid+3
    const int h0 = 4 * tid;

    // fc weights + bias into registers (28 floats)
    float4 w[NQ];
#pragma unroll
    for (int j = 0; j < NQ; j++) {
        w[j] = make_float4(__ldg(&fc_w[(h0 + 0) * NQ + j]),
                           __ldg(&fc_w[(h0 + 1) * NQ + j]),
                           __ldg(&fc_w[(h0 + 2) * NQ + j]),
                           __ldg(&fc_w[(h0 + 3) * NQ + j]));
    }
    float4 bv = make_float4(__ldg(&fc_b[h0]), __ldg(&fc_b[h0 + 1]),
                            __ldg(&fc_b[h0 + 2]), __ldg(&fc_b[h0 + 3]));

    const int step = gridDim.x * 4;
    for (int b0 = blockIdx.x * 4; b0 < B; b0 += step) {
        // ---- batch all loads first (MLP = 12) ----
        float4 h[4], qa[4], qb[4];
        const bool full = (b0 + 3 < B);
        if (full) {
#pragma unroll
            for (int r = 0; r < 4; r++)
                h[r] = __ldcs((const float4*)(hx + (size_t)(b0 + r) * HDIM) + tid);
#pragma unroll
            for (int r = 0; r < 4; r++) {
                const float4* qp = (const float4*)&g_qexp[(b0 + r) * QSTRIDE];
                qa[r] = qp[0];
                qb[r] = qp[1];
            }
#pragma unroll
            for (int r = 0; r < 4; r++) {
                float4 acc = bv;
                acc.x += qa[r].x*w[0].x; acc.y += qa[r].x*w[0].y; acc.z += qa[r].x*w[0].z; acc.w += qa[r].x*w[0].w;
                acc.x += qa[r].y*w[1].x; acc.y += qa[r].y*w[1].y; acc.z += qa[r].y*w[1].z; acc.w += qa[r].y*w[1].w;
                acc.x += qa[r].z*w[2].x; acc.y += qa[r].z*w[2].y; acc.z += qa[r].z*w[2].z; acc.w += qa[r].z*w[2].w;
                acc.x += qa[r].w*w[3].x; acc.y += qa[r].w*w[3].y; acc.z += qa[r].w*w[3].z; acc.w += qa[r].w*w[3].w;
                acc.x += qb[r].x*w[4].x; acc.y += qb[r].x*w[4].y; acc.z += qb[r].x*w[4].z; acc.w += qb[r].x*w[4].w;
                acc.x += qb[r].y*w[5].x; acc.y += qb[r].y*w[5].y; acc.z += qb[r].y*w[5].z; acc.w += qb[r].y*w[5].w;
                float4 v = h[r];
                v.x += acc.x; v.y += acc.y; v.z += acc.z; v.w += acc.w;
                __stcs((float4*)(out + (size_t)(b0 + r) * HDIM) + tid, v);
            }
        } else {
            for (int r = 0; r < 4; r++) {
                int b = b0 + r;
                if (b >= B) break;
                float4 hh = __ldcs((const float4*)(hx + (size_t)b * HDIM) + tid);
                const float4* qp = (const float4*)&g_qexp[b * QSTRIDE];
                float4 q0 = qp[0], q1 = qp[1];
                float4 acc = bv;
                acc.x += q0.x*w[0].x; acc.y += q0.x*w[0].y; acc.z += q0.x*w[0].z; acc.w += q0.x*w[0].w;
                acc.x += q0.y*w[1].x; acc.y += q0.y*w[1].y; acc.z += q0.y*w[1].z; acc.w += q0.y*w[1].w;
                acc.x += q0.z*w[2].x; acc.y += q0.z*w[2].y; acc.z += q0.z*w[2].z; acc.w += q0.z*w[2].w;
                acc.x += q0.w*w[3].x; acc.y += q0.w*w[3].y; acc.z += q0.w*w[3].z; acc.w += q0.w*w[3].w;
                acc.x += q1.x*w[4].x; acc.y += q1.x*w[4].y; acc.z += q1.x*w[4].z; acc.w += q1.x*w[4].w;
                acc.x += q1.y*w[5].x; acc.y += q1.y*w[5].y; acc.z += q1.y*w[5].z; acc.w += q1.y*w[5].w;
                hh.x += acc.x; hh.y += acc.y; hh.z += acc.z; hh.w += acc.w;
                __stcs((float4*)(out + (size_t)b * HDIM) + tid, hh);
            }
        }
    }
}

// ---- launch ----------------------------------------------------------------
extern "C" void kernel_launch(void* const* d_in, const int* in_sizes, int n_in,
                              void* d_out, int out_size) {
    const float* x    = (const float*)d_in[0];   // (B,6)
    const float* hx   = (const float*)d_in[1];   // (B,1024)
    const float* qw   = (const float*)d_in[2];   // (3,6)
    const float* fc_w = (const float*)d_in[3];   // (1024,6)
    const float* fc_b = (const float*)d_in[4];   // (1024,)
    float* out = (float*)d_out;

    int B = in_sizes[0] / NQ;
    if (B > MAXB) B = MAXB;

    // kernel 1: sim (16 rows per block)
    {
        int blocks = (B + 15) / 16;
        qsim_kernel<<<blocks, 256>>>(x, qw, B);
    }
    // kernel 2: stream (grid-stride, 4 rows per iteration)
    {
        int niter = (B + 3) / 4;
        int grid = 148 * 6;
        if (grid > niter) grid = niter;
        stream_kernel<<<grid, 256>>>(hx, fc_w, fc_b, out, B);
    }
}

// round 6
// speedup vs baseline: 1.3461x; 1.3461x over previous
#include <cuda_runtime.h>
#include <cstdint>

// ---------------------------------------------------------------------------
// QuantumRNNCell fused persistent kernel, v6:
//   out[b,h] = hx[b,h] + sum_j q[b,j] * fc_w[h,j] + fc_b[h]
// - Encoding state is a product state -> computed analytically (no gates).
// - Variational layers (RY + CNOT ring) via 32-lane warp-shuffle sim,
//   one row per warp (a[4] = 2 complex amps per lane).
// - hx streamed through a 3-stage cp.async smem pipeline so DRAM loads are
//   continuously in flight (incl. during the FMA+store phase).
// - fc weights/bias live in 28 registers per thread (fixed column group).
// ---------------------------------------------------------------------------

#define NQ 6
#define NLAYERS 3
#define HDIM 1024
#define TR 8          // rows per tile == warps per block
#define STAGES 3
#define TILE_F4 (TR * 256)            // float4s per tile (8 rows x 1KB)

__device__ __forceinline__ void cp_async16(uint32_t dst, const void* src) {
    asm volatile("cp.async.cg.shared.global [%0], [%1], 16;"
                 :: "r"(dst), "l"(src));
}
__device__ __forceinline__ void cp_commit() {
    asm volatile("cp.async.commit_group;");
}
__device__ __forceinline__ void cp_wait2() {
    asm volatile("cp.async.wait_group 2;" ::: "memory");
}

// ---- layer gates, 32-lane layout (validated R1-R3) -------------------------
// Lane L holds states s=L (a[0],a[1]) and s=L+32 (a[2],a[3]).
// Wire w acts on state bit (5-w); wire 0 = the a0/a1 split.
__device__ __forceinline__ void apply_ry(int w, float a[4], float c, float s,
                                         unsigned lane) {
    if (w == 0) {
        float nr0 = c * a[0] - s * a[2];
        float ni0 = c * a[1] - s * a[3];
        float nr1 = s * a[0] + c * a[2];
        float ni1 = s * a[1] + c * a[3];
        a[0] = nr0; a[1] = ni0; a[2] = nr1; a[3] = ni1;
    } else {
        int m = 1 << (5 - w);
        float sg = (lane & (unsigned)m) ? s : -s;
        float or0 = __shfl_xor_sync(0xFFFFFFFFu, a[0], m);
        float oi0 = __shfl_xor_sync(0xFFFFFFFFu, a[1], m);
        float or1 = __shfl_xor_sync(0xFFFFFFFFu, a[2], m);
        float oi1 = __shfl_xor_sync(0xFFFFFFFFu, a[3], m);
        a[0] = c * a[0] + sg * or0;
        a[1] = c * a[1] + sg * oi0;
        a[2] = c * a[2] + sg * or1;
        a[3] = c * a[3] + sg * oi1;
    }
}

__device__ __forceinline__ void apply_cnot_ring(int q, float a[4], unsigned lane) {
    if (q == 0) {
        a[2] = __shfl_xor_sync(0xFFFFFFFFu, a[2], 16);
        a[3] = __shfl_xor_sync(0xFFFFFFFFu, a[3], 16);
    } else if (q == 5) {
        if (lane & 1u) {
            float t;
            t = a[0]; a[0] = a[2]; a[2] = t;
            t = a[1]; a[1] = a[3]; a[3] = t;
        }
    } else {
        int cb = 5 - q;
        int tm = 1 << (4 - q);
        bool ctrl = (lane & (unsigned)(1 << cb)) != 0;
        float v0 = __shfl_xor_sync(0xFFFFFFFFu, a[0], tm);
        float v1 = __shfl_xor_sync(0xFFFFFFFFu, a[1], tm);
        float v2 = __shfl_xor_sync(0xFFFFFFFFu, a[2], tm);
        float v3 = __shfl_xor_sync(0xFFFFFFFFu, a[3], tm);
        if (ctrl) { a[0] = v0; a[1] = v1; a[2] = v2; a[3] = v3; }
    }
}

// ---- fused persistent kernel ------------------------------------------------
__global__ __launch_bounds__(256, 2)
void fused_kernel(const float* __restrict__ x,
                  const float* __restrict__ hx,
                  const float* __restrict__ qw,    // (3,6)
                  const float* __restrict__ fc_w,  // (1024,6)
                  const float* __restrict__ fc_b,  // (1024,)
                  float* __restrict__ out,
                  int B, int ntiles) {
    extern __shared__ unsigned char smem_raw[];
    float4* sbuf = (float4*)smem_raw;                      // STAGES * TILE_F4
    float*  sq   = (float*)(sbuf + STAGES * TILE_F4);      // 2 * TR * 8
    float*  swc  = sq + 2 * TR * 8;                        // 18
    float*  sws  = swc + NLAYERS * NQ;                     // 18

    const int tid = threadIdx.x;
    const int warp = tid >> 5;
    const unsigned lane = tid & 31u;
    const int stride = gridDim.x;
    const int maxf4 = B * 256 - 1;       // last valid float4 index in hx

    // ---- fc weights + bias into registers (28 floats) ----
    const int h0 = 4 * tid;
    float4 w[NQ];
#pragma unroll
    for (int j = 0; j < NQ; j++) {
        w[j] = make_float4(__ldg(&fc_w[(h0 + 0) * NQ + j]),
                           __ldg(&fc_w[(h0 + 1) * NQ + j]),
                           __ldg(&fc_w[(h0 + 2) * NQ + j]),
                           __ldg(&fc_w[(h0 + 3) * NQ + j]));
    }
    float4 bv = make_float4(__ldg(&fc_b[h0]), __ldg(&fc_b[h0 + 1]),
                            __ldg(&fc_b[h0 + 2]), __ldg(&fc_b[h0 + 3]));

    if (tid < NLAYERS * NQ) {
        float s, c;
        __sincosf(__ldg(&qw[tid]) * 0.5f, &s, &c);
        swc[tid] = c; sws[tid] = s;
    }
    __syncthreads();

    // ---- cp.async prologue: stages 0..STAGES-2 ----
#pragma unroll
    for (int p = 0; p < STAGES - 1; p++) {
        int t = blockIdx.x + p * stride;
        if (t < ntiles) {
            uint32_t dstb = (uint32_t)__cvta_generic_to_shared(&sbuf[p * TILE_F4]);
            const float4* srcb = (const float4*)hx;
            int base = t * TILE_F4;
#pragma unroll
            for (int k = 0; k < TR; k++) {
                int gi = min(base + k * 256 + tid, maxf4);
                cp_async16(dstb + (uint32_t)(k * 256 + tid) * 16u, srcb + gi);
            }
        }
        cp_commit();
    }

    int it = 0;
    for (int t = blockIdx.x; t < ntiles; t += stride, it++) {
        // ---- issue stage it+STAGES-1 ----
        {
            int t2 = t + (STAGES - 1) * stride;
            if (t2 < ntiles) {
                int bufn = (it + STAGES - 1) % STAGES;
                uint32_t dstb = (uint32_t)__cvta_generic_to_shared(&sbuf[bufn * TILE_F4]);
                const float4* srcb = (const float4*)hx;
                int base = t2 * TILE_F4;
#pragma unroll
                for (int k = 0; k < TR; k++) {
                    int gi = min(base + k * 256 + tid, maxf4);
                    cp_async16(dstb + (uint32_t)(k * 256 + tid) * 16u, srcb + gi);
                }
            }
            cp_commit();
        }

        // ---- sim: this warp handles row t*TR + warp ----
        {
            const int b = min(t * TR + warp, B - 1);

            float cx[NQ], sx[NQ];
#pragma unroll
            for (int j = 0; j < NQ; j++) {
                __sincosf(__ldg(&x[b * NQ + j]) * 0.5f, &sx[j], &cx[j]);
            }

            // analytic product-state encoding: per-wire v = RZ*RY*RX|0>
            float v0r[NQ], v0i[NQ], v1r[NQ], v1i[NQ];
#pragma unroll
            for (int iw = 0; iw < NQ; iw++) {
                int j1 = (iw + 1 > 5) ? iw - 5 : iw + 1;
                int j2 = (iw + 2 > 5) ? iw - 4 : iw + 2;
                float ar = cx[j1] * cx[iw];     // c*cx
                float ai = sx[j1] * sx[iw];     // s*sx
                float br = sx[j1] * cx[iw];     // s*cx
                float bi = -cx[j1] * sx[iw];    // -c*sx
                float cz = cx[j2], sz = sx[j2];
                v0r[iw] = ar * cz + ai * sz;    // v0 * (cz - i sz)
                v0i[iw] = ai * cz - ar * sz;
                v1r[iw] = br * cz - bi * sz;    // v1 * (cz + i sz)
                v1i[iw] = bi * cz + br * sz;
            }

            // f = prod over wires 1..5, bit of wire w2 = lane bit (5-w2)
            float fr, fi;
            {
                bool bs = (lane & 16u) != 0;    // wire 1 -> lane bit 4
                fr = bs ? v1r[1] : v0r[1];
                fi = bs ? v1i[1] : v0i[1];
            }
#pragma unroll
            for (int w2 = 2; w2 <= 5; w2++) {
                bool bs = (lane & (1u << (5 - w2))) != 0;
                float tr = bs ? v1r[w2] : v0r[w2];
                float ti = bs ? v1i[w2] : v0i[w2];
                float nr = fr * tr - fi * ti;
                float ni = fr * ti + fi * tr;
                fr = nr; fi = ni;
            }
            float a[4];
            a[0] = v0r[0] * fr - v0i[0] * fi;   // state bit5 = 0
            a[1] = v0r[0] * fi + v0i[0] * fr;
            a[2] = v1r[0] * fr - v1i[0] * fi;   // state bit5 = 1
            a[3] = v1r[0] * fi + v1i[0] * fr;

            // variational layers
#pragma unroll
            for (int l = 0; l < NLAYERS; l++) {
#pragma unroll
                for (int q = 0; q < NQ; q++)
                    apply_ry(q, a, swc[l * NQ + q], sws[l * NQ + q], lane);
#pragma unroll
                for (int q = 0; q < NQ; q++) apply_cnot_ring(q, a, lane);
            }

            // PauliZ expvals
            float p0 = a[0] * a[0] + a[1] * a[1];
            float p1 = a[2] * a[2] + a[3] * a[3];
            float e[NQ];
            e[0] = p0 - p1;
#pragma unroll
            for (int j = 1; j < NQ; j++) {
                float sg = (lane & (unsigned)(1 << (5 - j))) ? -1.0f : 1.0f;
                e[j] = sg * (p0 + p1);
            }
#pragma unroll
            for (int off = 16; off; off >>= 1) {
#pragma unroll
                for (int j = 0; j < NQ; j++)
                    e[j] += __shfl_xor_sync(0xFFFFFFFFu, e[j], off);
            }
            if (lane == 0) {
                float* dst = &sq[(it & 1) * (TR * 8) + warp * 8];
#pragma unroll
                for (int j = 0; j < NQ; j++) dst[j] = e[j];
            }
        }

        cp_wait2();            // tile t's cp.async group complete
        __syncthreads();       // sq + smem buffer visible block-wide

        // ---- FMA + store tile t from smem stage it%STAGES ----
        {
            const float4* buf = &sbuf[(it % STAGES) * TILE_F4];
            const float* sqr = &sq[(it & 1) * (TR * 8)];
            const int row0 = t * TR;
#pragma unroll
            for (int r = 0; r < TR; r++) {
                int b = row0 + r;
                if (b >= B) break;
                float q0 = sqr[r * 8 + 0], q1 = sqr[r * 8 + 1], q2 = sqr[r * 8 + 2];
                float q3 = sqr[r * 8 + 3], q4 = sqr[r * 8 + 4], q5 = sqr[r * 8 + 5];
                float4 v = buf[r * 256 + tid];
                float4 acc = bv;
                acc.x += q0*w[0].x; acc.y += q0*w[0].y; acc.z += q0*w[0].z; acc.w += q0*w[0].w;
                acc.x += q1*w[1].x; acc.y += q1*w[1].y; acc.z += q1*w[1].z; acc.w += q1*w[1].w;
                acc.x += q2*w[2].x; acc.y += q2*w[2].y; acc.z += q2*w[2].z; acc.w += q2*w[2].w;
                acc.x += q3*w[3].x; acc.y += q3*w[3].y; acc.z += q3*w[3].z; acc.w += q3*w[3].w;
                acc.x += q4*w[4].x; acc.y += q4*w[4].y; acc.z += q4*w[4].z; acc.w += q4*w[4].w;
                acc.x += q5*w[5].x; acc.y += q5*w[5].y; acc.z += q5*w[5].z; acc.w += q5*w[5].w;
                v.x += acc.x; v.y += acc.y; v.z += acc.z; v.w += acc.w;
                __stcs((float4*)(out + (size_t)b * HDIM) + tid, v);
            }
        }
    }
}

// ---- launch ----------------------------------------------------------------
extern "C" void kernel_launch(void* const* d_in, const int* in_sizes, int n_in,
                              void* d_out, int out_size) {
    const float* x    = (const float*)d_in[0];   // (B,6)
    const float* hx   = (const float*)d_in[1];   // (B,1024)
    const float* qw   = (const float*)d_in[2];   // (3,6)
    const float* fc_w = (const float*)d_in[3];   // (1024,6)
    const float* fc_b = (const float*)d_in[4];   // (1024,)
    float* out = (float*)d_out;

    int B = in_sizes[0] / NQ;
    int ntiles = (B + TR - 1) / TR;

    const int smem_bytes = STAGES * TILE_F4 * 16 + 2 * TR * 8 * 4
                         + 2 * NLAYERS * NQ * 4;

    static int attr_set = 0;
    // setting the attribute is idempotent and deterministic; do it every call
    cudaFuncSetAttribute(fused_kernel,
                         cudaFuncAttributeMaxDynamicSharedMemorySize,
                         smem_bytes);
    (void)attr_set;

    int grid = 148 * 2;
    if (grid > ntiles) grid = ntiles;
    fused_kernel<<<grid, 256, smem_bytes>>>(x, hx, qw, fc_w, fc_b, out, B, ntiles);
}

// round 7
// speedup vs baseline: 1.4091x; 1.0468x over previous
#include <cuda_runtime.h>
#include <cstdint>

// ---------------------------------------------------------------------------
// QuantumRNNCell fused persistent kernel, v7:
//   out[b,h] = hx[b,h] + sum_j q[b,j] * fc_w[h,j] + fc_b[h]
// - Encoding computed analytically (product state), no gates.
// - Variational layers simulated 2 rows per warp (16 lanes/row, 4 complex
//   amps per lane; state bits 5,4 in registers, bits 3..0 across lanes).
//   Only warps 0..3 sim (8 rows/tile); warps 4..7 skip straight to barrier.
// - hx streamed through a 2-stage cp.async pipeline (64KB smem -> 3 CTAs/SM).
//   While tile t is FMA'd+stored, tile t+1's loads are in flight.
// - fc weights/bias in 28 registers per thread (fixed column group).
// ---------------------------------------------------------------------------

#define NQ 6
#define NLAYERS 3
#define HDIM 1024
#define TR 8          // rows per tile
#define STAGES 2
#define TILE_F4 (TR * 256)            // float4s per tile (8 rows x 1KB)

__device__ __forceinline__ void cp_async16(uint32_t dst, const void* src) {
    asm volatile("cp.async.cg.shared.global [%0], [%1], 16;"
                 :: "r"(dst), "l"(src));
}
__device__ __forceinline__ void cp_commit() {
    asm volatile("cp.async.commit_group;");
}
__device__ __forceinline__ void cp_wait1() {
    asm volatile("cp.async.wait_group 1;" ::: "memory");
}

// ---- packed (2-row) gate helpers, validated in R4 --------------------------
// a[8] = {re,im} x hi2(0..3); hi2 bit1 = state bit5, hi2 bit0 = state bit4.
// State bits 3..0 = lane16 bits 3..0.
__device__ __forceinline__ void ry_pair(float a[8], int i0, int i1, float c, float s) {
    float re0 = a[2*i0], im0 = a[2*i0+1], re1 = a[2*i1], im1 = a[2*i1+1];
    a[2*i0]   = c*re0 - s*re1;
    a[2*i0+1] = c*im0 - s*im1;
    a[2*i1]   = s*re0 + c*re1;
    a[2*i1+1] = s*im0 + c*im1;
}
__device__ __forceinline__ void ry_shfl(float a[8], int m, float c, float s, unsigned lane) {
    float sg = (lane & (unsigned)m) ? s : -s;
#pragma unroll
    for (int k = 0; k < 4; k++) {
        float orr = __shfl_xor_sync(0xFFFFFFFFu, a[2*k],   m);
        float oii = __shfl_xor_sync(0xFFFFFFFFu, a[2*k+1], m);
        a[2*k]   = c*a[2*k]   + sg*orr;
        a[2*k+1] = c*a[2*k+1] + sg*oii;
    }
}
__device__ __forceinline__ void apply_ry(int w, float a[8], float c, float s, unsigned lane) {
    if (w == 0)      { ry_pair(a, 0, 2, c, s); ry_pair(a, 1, 3, c, s); }
    else if (w == 1) { ry_pair(a, 0, 1, c, s); ry_pair(a, 2, 3, c, s); }
    else             ry_shfl(a, 1 << (5 - w), c, s, lane);
}

__device__ __forceinline__ void apply_cnot_ring(int q, float a[8], unsigned lane) {
    if (q == 0) {
        // control bit5 (hi2 {2,3}), target bit4: swap hi2 2 <-> 3
        float t;
        t = a[4]; a[4] = a[6]; a[6] = t;
        t = a[5]; a[5] = a[7]; a[7] = t;
    } else if (q == 1) {
        // control bit4 (hi2 {1,3}), target bit3: shuffle mask 8, unconditional
#pragma unroll
        for (int k = 1; k < 4; k += 2) {
            a[2*k]   = __shfl_xor_sync(0xFFFFFFFFu, a[2*k],   8);
            a[2*k+1] = __shfl_xor_sync(0xFFFFFFFFu, a[2*k+1], 8);
        }
    } else if (q == 5) {
        // control bit0 (lane&1), target bit5: swap hi2 {0,1} <-> {2,3}
        if (lane & 1u) {
            float t;
            t = a[0]; a[0] = a[4]; a[4] = t;
            t = a[1]; a[1] = a[5]; a[5] = t;
            t = a[2]; a[2] = a[6]; a[6] = t;
            t = a[3]; a[3] = a[7]; a[7] = t;
        }
    } else {
        // q in {2,3,4}: control lane bit (5-q), target shuffle mask 1<<(4-q)
        int cb = 1 << (5 - q);
        int tm = 1 << (4 - q);
        bool ctrl = (lane & (unsigned)cb) != 0;
#pragma unroll
        for (int k = 0; k < 4; k++) {
            float vr = __shfl_xor_sync(0xFFFFFFFFu, a[2*k],   tm);
            float vi = __shfl_xor_sync(0xFFFFFFFFu, a[2*k+1], tm);
            if (ctrl) { a[2*k] = vr; a[2*k+1] = vi; }
        }
    }
}

// ---- fused persistent kernel ------------------------------------------------
__global__ __launch_bounds__(256, 3)
void fused_kernel(const float* __restrict__ x,
                  const float* __restrict__ hx,
                  const float* __restrict__ qw,    // (3,6)
                  const float* __restrict__ fc_w,  // (1024,6)
                  const float* __restrict__ fc_b,  // (1024,)
                  float* __restrict__ out,
                  int B, int ntiles) {
    extern __shared__ unsigned char smem_raw[];
    float4* sbuf = (float4*)smem_raw;                      // STAGES * TILE_F4
    float*  sq   = (float*)(sbuf + STAGES * TILE_F4);      // TR * 8
    float*  swc  = sq + TR * 8;                            // 18
    float*  sws  = swc + NLAYERS * NQ;                     // 18

    const int tid = threadIdx.x;
    const int warp = tid >> 5;
    const unsigned lane = tid & 31u;
    const unsigned lane16 = lane & 15u;
    const int half = (int)(lane >> 4);
    const int stride = gridDim.x;
    const int maxf4 = B * 256 - 1;

    // ---- fc weights + bias into registers ----
    const int h0 = 4 * tid;
    float4 w[NQ];
#pragma unroll
    for (int j = 0; j < NQ; j++) {
        w[j] = make_float4(__ldg(&fc_w[(h0 + 0) * NQ + j]),
                           __ldg(&fc_w[(h0 + 1) * NQ + j]),
                           __ldg(&fc_w[(h0 + 2) * NQ + j]),
                           __ldg(&fc_w[(h0 + 3) * NQ + j]));
    }
    float4 bv = make_float4(__ldg(&fc_b[h0]), __ldg(&fc_b[h0 + 1]),
                            __ldg(&fc_b[h0 + 2]), __ldg(&fc_b[h0 + 3]));

    if (tid < NLAYERS * NQ) {
        float s, c;
        __sincosf(__ldg(&qw[tid]) * 0.5f, &s, &c);
        swc[tid] = c; sws[tid] = s;
    }
    __syncthreads();

    // ---- prologue: issue tile t0 into stage 0 ----
    {
        int t = blockIdx.x;
        if (t < ntiles) {
            uint32_t dstb = (uint32_t)__cvta_generic_to_shared(&sbuf[0]);
            const float4* srcb = (const float4*)hx;
            int base = t * TILE_F4;
#pragma unroll
            for (int k = 0; k < TR; k++) {
                int gi = min(base + k * 256 + tid, maxf4);
                cp_async16(dstb + (uint32_t)(k * 256 + tid) * 16u, srcb + gi);
            }
        }
        cp_commit();
    }

    int it = 0;
    for (int t = blockIdx.x; t < ntiles; t += stride, it++) {
        // ---- issue tile t+stride into the other stage ----
        {
            int t2 = t + stride;
            if (t2 < ntiles) {
                uint32_t dstb = (uint32_t)__cvta_generic_to_shared(
                    &sbuf[((it + 1) & 1) * TILE_F4]);
                const float4* srcb = (const float4*)hx;
                int base = t2 * TILE_F4;
#pragma unroll
                for (int k = 0; k < TR; k++) {
                    int gi = min(base + k * 256 + tid, maxf4);
                    cp_async16(dstb + (uint32_t)(k * 256 + tid) * 16u, srcb + gi);
                }
            }
            cp_commit();
        }

        // ---- sim (warps 0..3): 2 rows per warp, analytic encoding ----
        if (warp < 4) {
            const int row = warp * 2 + half;
            const int b = min(t * TR + row, B - 1);

            float cx[NQ], sx[NQ];
#pragma unroll
            for (int j = 0; j < NQ; j++) {
                __sincosf(__ldg(&x[b * NQ + j]) * 0.5f, &sx[j], &cx[j]);
            }

            // per-wire v = RZ*RY*RX|0>  (v0 = amp for bit 0, v1 for bit 1)
            float v0r[NQ], v0i[NQ], v1r[NQ], v1i[NQ];
#pragma unroll
            for (int iw = 0; iw < NQ; iw++) {
                int j1 = (iw + 1 > 5) ? iw - 5 : iw + 1;
                int j2 = (iw + 2 > 5) ? iw - 4 : iw + 2;
                float ar = cx[j1] * cx[iw];
                float ai = sx[j1] * sx[iw];
                float br = sx[j1] * cx[iw];
                float bi = -cx[j1] * sx[iw];
                float cz = cx[j2], sz = sx[j2];
                v0r[iw] = ar * cz + ai * sz;
                v0i[iw] = ai * cz - ar * sz;
                v1r[iw] = br * cz - bi * sz;
                v1i[iw] = bi * cz + br * sz;
            }

            // f = prod over wires 2..5; wire w bit = lane16 bit (5-w)
            float fr, fi;
            {
                bool bs = (lane16 & 8u) != 0;   // wire 2 -> bit 3
                fr = bs ? v1r[2] : v0r[2];
                fi = bs ? v1i[2] : v0i[2];
            }
#pragma unroll
            for (int w2 = 3; w2 <= 5; w2++) {
                bool bs = (lane16 & (1u << (5 - w2))) != 0;
                float tr = bs ? v1r[w2] : v0r[w2];
                float ti = bs ? v1i[w2] : v0i[w2];
                float nr = fr * tr - fi * ti;
                float ni = fr * ti + fi * tr;
                fr = nr; fi = ni;
            }

            // amplitudes per hi2 k: v[0][k>>1] * v[1][k&1] * f
            float a[8];
#pragma unroll
            for (int k = 0; k < 4; k++) {
                float u0r = (k & 2) ? v1r[0] : v0r[0];
                float u0i = (k & 2) ? v1i[0] : v0i[0];
                float u1r = (k & 1) ? v1r[1] : v0r[1];
                float u1i = (k & 1) ? v1i[1] : v0i[1];
                float gr = u0r * u1r - u0i * u1i;
                float gi = u0r * u1i + u0i * u1r;
                a[2*k]   = gr * fr - gi * fi;
                a[2*k+1] = gr * fi + gi * fr;
            }

            // variational layers
#pragma unroll
            for (int l = 0; l < NLAYERS; l++) {
#pragma unroll
                for (int q = 0; q < NQ; q++)
                    apply_ry(q, a, swc[l * NQ + q], sws[l * NQ + q], lane);
#pragma unroll
                for (int q = 0; q < NQ; q++) apply_cnot_ring(q, a, lane);
            }

            // PauliZ expvals
            float p0 = a[0]*a[0] + a[1]*a[1];
            float p1 = a[2]*a[2] + a[3]*a[3];
            float p2 = a[4]*a[4] + a[5]*a[5];
            float p3 = a[6]*a[6] + a[7]*a[7];
            float ptot = p0 + p1 + p2 + p3;

            float e[NQ];
            e[0] = (p0 + p1) - (p2 + p3);   // wire0: hi2 bit1
            e[1] = (p0 - p1) + (p2 - p3);   // wire1: hi2 bit0
#pragma unroll
            for (int j = 2; j < NQ; j++) {
                float sg = (lane16 & (unsigned)(1 << (5 - j))) ? -1.0f : 1.0f;
                e[j] = sg * ptot;
            }
#pragma unroll
            for (int off = 8; off; off >>= 1) {
#pragma unroll
                for (int j = 0; j < NQ; j++)
                    e[j] += __shfl_xor_sync(0xFFFFFFFFu, e[j], off);
            }
            if (lane16 == 0) {
#pragma unroll
                for (int j = 0; j < NQ; j++) sq[row * 8 + j] = e[j];
                sq[row * 8 + 6] = 0.0f;
                sq[row * 8 + 7] = 0.0f;
            }
        }

        cp_wait1();            // tile t's group complete (t+1 may stay pending)
        __syncthreads();       // sq + stage visible block-wide

        // ---- FMA + store tile t from stage it%2 ----
        {
            const float4* buf = &sbuf[(it & 1) * TILE_F4];
            const int row0 = t * TR;
#pragma unroll
            for (int r = 0; r < TR; r++) {
                int b = row0 + r;
                if (b >= B) break;
                float4 qa = *(const float4*)&sq[r * 8];
                float4 qb = *(const float4*)&sq[r * 8 + 4];
                float4 v = buf[r * 256 + tid];
                float4 acc = bv;
                acc.x += qa.x*w[0].x; acc.y += qa.x*w[0].y; acc.z += qa.x*w[0].z; acc.w += qa.x*w[0].w;
                acc.x += qa.y*w[1].x; acc.y += qa.y*w[1].y; acc.z += qa.y*w[1].z; acc.w += qa.y*w[1].w;
                acc.x += qa.z*w[2].x; acc.y += qa.z*w[2].y; acc.z += qa.z*w[2].z; acc.w += qa.z*w[2].w;
                acc.x += qa.w*w[3].x; acc.y += qa.w*w[3].y; acc.z += qa.w*w[3].z; acc.w += qa.w*w[3].w;
                acc.x += qb.x*w[4].x; acc.y += qb.x*w[4].y; acc.z += qb.x*w[4].z; acc.w += qb.x*w[4].w;
                acc.x += qb.y*w[5].x; acc.y += qb.y*w[5].y; acc.z += qb.y*w[5].z; acc.w += qb.y*w[5].w;
                v.x += acc.x; v.y += acc.y; v.z += acc.z; v.w += acc.w;
                __stcs((float4*)(out + (size_t)b * HDIM) + tid, v);
            }
        }
        __syncthreads();       // protect stage (it%2) from next iter's cp.async
    }
}

// ---- launch ----------------------------------------------------------------
extern "C" void kernel_launch(void* const* d_in, const int* in_sizes, int n_in,
                              void* d_out, int out_size) {
    const float* x    = (const float*)d_in[0];   // (B,6)
    const float* hx   = (const float*)d_in[1];   // (B,1024)
    const float* qw   = (const float*)d_in[2];   // (3,6)
    const float* fc_w = (const float*)d_in[3];   // (1024,6)
    const float* fc_b = (const float*)d_in[4];   // (1024,)
    float* out = (float*)d_out;

    int B = in_sizes[0] / NQ;
    int ntiles = (B + TR - 1) / TR;

    const int smem_bytes = STAGES * TILE_F4 * 16 + TR * 8 * 4
                         + 2 * NLAYERS * NQ * 4;

    cudaFuncSetAttribute(fused_kernel,
                         cudaFuncAttributeMaxDynamicSharedMemorySize,
                         smem_bytes);

    int grid = 148 * 3;
    if (grid > ntiles) grid = ntiles;
    fused_kernel<<<grid, 256, smem_bytes>>>(x, hx, qw, fc_w, fc_b, out, B, ntiles);
}

// round 8
// speedup vs baseline: 1.5380x; 1.0915x over previous
#include <cuda_runtime.h>
#include <cstdint>

// ---------------------------------------------------------------------------
// QuantumRNNCell fused persistent kernel, v8 (warp-specialized):
//   out[b,h] = hx[b,h] + sum_j q[b,j] * fc_w[h,j] + fc_b[h]
// Block = 384 threads:
//   warps 0..3  : sim warps. Packed 2-rows-per-warp 6-qubit sim (16 lanes/row,
//                 4 complex amps/lane), analytic product-state encoding.
//                 Iteration it: simulate tile t+stride into sq[(it+1)&1].
//   warps 4..11 : stream warps (256 threads, fixed column group each,
//                 fc weights+bias in 28 registers). Iteration it:
//                 cp.async tile t+stride into stage[(it+1)&1], then
//                 FMA+store tile t from stage[it&1] + sq[it&1].
// ONE __syncthreads per tile; loads for the next tile are always in flight
// during the FMA/store phase. 2-stage smem pipeline (64KB) -> 2 CTAs/SM.
// ---------------------------------------------------------------------------

#define NQ 6
#define NLAYERS 3
#define HDIM 1024
#define TR 8
#define STAGES 2
#define TILE_F4 (TR * 256)       // 2048 float4 per tile
#define NSIMW 4                  // sim warps
#define NTHREADS 384

__device__ __forceinline__ void cp_async16(uint32_t dst, const void* src) {
    asm volatile("cp.async.cg.shared.global [%0], [%1], 16;"
                 :: "r"(dst), "l"(src));
}
__device__ __forceinline__ void cp_commit() {
    asm volatile("cp.async.commit_group;");
}
__device__ __forceinline__ void cp_wait1() {
    asm volatile("cp.async.wait_group 1;" ::: "memory");
}

// ---- packed (2-row) gate helpers (validated R4/R7) -------------------------
// a[8] = {re,im} x hi2(0..3); hi2 bit1 = state bit5, hi2 bit0 = state bit4.
// State bits 3..0 = lane16 bits 3..0.
__device__ __forceinline__ void ry_pair(float a[8], int i0, int i1, float c, float s) {
    float re0 = a[2*i0], im0 = a[2*i0+1], re1 = a[2*i1], im1 = a[2*i1+1];
    a[2*i0]   = c*re0 - s*re1;
    a[2*i0+1] = c*im0 - s*im1;
    a[2*i1]   = s*re0 + c*re1;
    a[2*i1+1] = s*im0 + c*im1;
}
__device__ __forceinline__ void ry_shfl(float a[8], int m, float c, float s, unsigned lane) {
    float sg = (lane & (unsigned)m) ? s : -s;
#pragma unroll
    for (int k = 0; k < 4; k++) {
        float orr = __shfl_xor_sync(0xFFFFFFFFu, a[2*k],   m);
        float oii = __shfl_xor_sync(0xFFFFFFFFu, a[2*k+1], m);
        a[2*k]   = c*a[2*k]   + sg*orr;
        a[2*k+1] = c*a[2*k+1] + sg*oii;
    }
}
__device__ __forceinline__ void apply_ry(int w, float a[8], float c, float s, unsigned lane) {
    if (w == 0)      { ry_pair(a, 0, 2, c, s); ry_pair(a, 1, 3, c, s); }
    else if (w == 1) { ry_pair(a, 0, 1, c, s); ry_pair(a, 2, 3, c, s); }
    else             ry_shfl(a, 1 << (5 - w), c, s, lane);
}

__device__ __forceinline__ void apply_cnot_ring(int q, float a[8], unsigned lane) {
    if (q == 0) {
        float t;
        t = a[4]; a[4] = a[6]; a[6] = t;
        t = a[5]; a[5] = a[7]; a[7] = t;
    } else if (q == 1) {
#pragma unroll
        for (int k = 1; k < 4; k += 2) {
            a[2*k]   = __shfl_xor_sync(0xFFFFFFFFu, a[2*k],   8);
            a[2*k+1] = __shfl_xor_sync(0xFFFFFFFFu, a[2*k+1], 8);
        }
    } else if (q == 5) {
        if (lane & 1u) {
            float t;
            t = a[0]; a[0] = a[4]; a[4] = t;
            t = a[1]; a[1] = a[5]; a[5] = t;
            t = a[2]; a[2] = a[6]; a[6] = t;
            t = a[3]; a[3] = a[7]; a[7] = t;
        }
    } else {
        int cb = 1 << (5 - q);
        int tm = 1 << (4 - q);
        bool ctrl = (lane & (unsigned)cb) != 0;
#pragma unroll
        for (int k = 0; k < 4; k++) {
            float vr = __shfl_xor_sync(0xFFFFFFFFu, a[2*k],   tm);
            float vi = __shfl_xor_sync(0xFFFFFFFFu, a[2*k+1], tm);
            if (ctrl) { a[2*k] = vr; a[2*k+1] = vi; }
        }
    }
}

// ---- full sim for one tile-row pair (validated R7) -------------------------
__device__ __forceinline__ void sim_rows(
    const float* __restrict__ x, const float* swc, const float* sws,
    float* sqdst,              // sq buffer base (TR rows x 8 floats)
    int trow,                  // tile-local row this half handles
    int b,                     // clamped batch row
    unsigned lane, unsigned lane16) {
    float cx[NQ], sx[NQ];
#pragma unroll
    for (int j = 0; j < NQ; j++) {
        __sincosf(__ldg(&x[b * NQ + j]) * 0.5f, &sx[j], &cx[j]);
    }

    // per-wire v = RZ*RY*RX|0>
    float v0r[NQ], v0i[NQ], v1r[NQ], v1i[NQ];
#pragma unroll
    for (int iw = 0; iw < NQ; iw++) {
        int j1 = (iw + 1 > 5) ? iw - 5 : iw + 1;
        int j2 = (iw + 2 > 5) ? iw - 4 : iw + 2;
        float ar = cx[j1] * cx[iw];
        float ai = sx[j1] * sx[iw];
        float br = sx[j1] * cx[iw];
        float bi = -cx[j1] * sx[iw];
        float cz = cx[j2], sz = sx[j2];
        v0r[iw] = ar * cz + ai * sz;
        v0i[iw] = ai * cz - ar * sz;
        v1r[iw] = br * cz - bi * sz;
        v1i[iw] = bi * cz + br * sz;
    }

    // f = prod over wires 2..5; wire w bit = lane16 bit (5-w)
    float fr, fi;
    {
        bool bs = (lane16 & 8u) != 0;
        fr = bs ? v1r[2] : v0r[2];
        fi = bs ? v1i[2] : v0i[2];
    }
#pragma unroll
    for (int w2 = 3; w2 <= 5; w2++) {
        bool bs = (lane16 & (1u << (5 - w2))) != 0;
        float tr = bs ? v1r[w2] : v0r[w2];
        float ti = bs ? v1i[w2] : v0i[w2];
        float nr = fr * tr - fi * ti;
        float ni = fr * ti + fi * tr;
        fr = nr; fi = ni;
    }

    float a[8];
#pragma unroll
    for (int k = 0; k < 4; k++) {
        float u0r = (k & 2) ? v1r[0] : v0r[0];
        float u0i = (k & 2) ? v1i[0] : v0i[0];
        float u1r = (k & 1) ? v1r[1] : v0r[1];
        float u1i = (k & 1) ? v1i[1] : v0i[1];
        float gr = u0r * u1r - u0i * u1i;
        float gi = u0r * u1i + u0i * u1r;
        a[2*k]   = gr * fr - gi * fi;
        a[2*k+1] = gr * fi + gi * fr;
    }

#pragma unroll
    for (int l = 0; l < NLAYERS; l++) {
#pragma unroll
        for (int q = 0; q < NQ; q++)
            apply_ry(q, a, swc[l * NQ + q], sws[l * NQ + q], lane);
#pragma unroll
        for (int q = 0; q < NQ; q++) apply_cnot_ring(q, a, lane);
    }

    float p0 = a[0]*a[0] + a[1]*a[1];
    float p1 = a[2]*a[2] + a[3]*a[3];
    float p2 = a[4]*a[4] + a[5]*a[5];
    float p3 = a[6]*a[6] + a[7]*a[7];
    float ptot = p0 + p1 + p2 + p3;

    float e[NQ];
    e[0] = (p0 + p1) - (p2 + p3);
    e[1] = (p0 - p1) + (p2 - p3);
#pragma unroll
    for (int j = 2; j < NQ; j++) {
        float sg = (lane16 & (unsigned)(1 << (5 - j))) ? -1.0f : 1.0f;
        e[j] = sg * ptot;
    }
#pragma unroll
    for (int off = 8; off; off >>= 1) {
#pragma unroll
        for (int j = 0; j < NQ; j++)
            e[j] += __shfl_xor_sync(0xFFFFFFFFu, e[j], off);
    }
    if (lane16 == 0) {
#pragma unroll
        for (int j = 0; j < NQ; j++) sqdst[trow * 8 + j] = e[j];
        sqdst[trow * 8 + 6] = 0.0f;
        sqdst[trow * 8 + 7] = 0.0f;
    }
}

// ---- fused persistent kernel ------------------------------------------------
__global__ __launch_bounds__(NTHREADS, 2)
void fused_kernel(const float* __restrict__ x,
                  const float* __restrict__ hx,
                  const float* __restrict__ qw,    // (3,6)
                  const float* __restrict__ fc_w,  // (1024,6)
                  const float* __restrict__ fc_b,  // (1024,)
                  float* __restrict__ out,
                  int B, int ntiles) {
    extern __shared__ unsigned char smem_raw[];
    float4* sbuf = (float4*)smem_raw;                      // STAGES * TILE_F4
    float*  sq   = (float*)(sbuf + STAGES * TILE_F4);      // 2 * TR * 8
    float*  swc  = sq + 2 * TR * 8;                        // 18
    float*  sws  = swc + NLAYERS * NQ;                     // 18

    const int tid = threadIdx.x;
    const int warp = tid >> 5;
    const unsigned lane = tid & 31u;
    const unsigned lane16 = lane & 15u;
    const int half = (int)(lane >> 4);
    const int stride = gridDim.x;
    const int maxf4 = B * 256 - 1;
    const bool is_stream = (warp >= NSIMW);
    const int st = tid - NSIMW * 32;       // stream thread id 0..255

    // ---- stream threads: fc weights + bias into registers ----
    float4 w0, w1, w2, w3, w4, w5, bv;
    if (is_stream) {
        const int h0 = 4 * st;
        w0 = make_float4(__ldg(&fc_w[(h0+0)*NQ+0]), __ldg(&fc_w[(h0+1)*NQ+0]),
                         __ldg(&fc_w[(h0+2)*NQ+0]), __ldg(&fc_w[(h0+3)*NQ+0]));
        w1 = make_float4(__ldg(&fc_w[(h0+0)*NQ+1]), __ldg(&fc_w[(h0+1)*NQ+1]),
                         __ldg(&fc_w[(h0+2)*NQ+1]), __ldg(&fc_w[(h0+3)*NQ+1]));
        w2 = make_float4(__ldg(&fc_w[(h0+0)*NQ+2]), __ldg(&fc_w[(h0+1)*NQ+2]),
                         __ldg(&fc_w[(h0+2)*NQ+2]), __ldg(&fc_w[(h0+3)*NQ+2]));
        w3 = make_float4(__ldg(&fc_w[(h0+0)*NQ+3]), __ldg(&fc_w[(h0+1)*NQ+3]),
                         __ldg(&fc_w[(h0+2)*NQ+3]), __ldg(&fc_w[(h0+3)*NQ+3]));
        w4 = make_float4(__ldg(&fc_w[(h0+0)*NQ+4]), __ldg(&fc_w[(h0+1)*NQ+4]),
                         __ldg(&fc_w[(h0+2)*NQ+4]), __ldg(&fc_w[(h0+3)*NQ+4]));
        w5 = make_float4(__ldg(&fc_w[(h0+0)*NQ+5]), __ldg(&fc_w[(h0+1)*NQ+5]),
                         __ldg(&fc_w[(h0+2)*NQ+5]), __ldg(&fc_w[(h0+3)*NQ+5]));
        bv = make_float4(__ldg(&fc_b[h0]), __ldg(&fc_b[h0+1]),
                         __ldg(&fc_b[h0+2]), __ldg(&fc_b[h0+3]));
    }
    if (tid < NLAYERS * NQ) {
        float s, c;
        __sincosf(__ldg(&qw[tid]) * 0.5f, &s, &c);
        swc[tid] = c; sws[tid] = s;
    }
    __syncthreads();

    const int t0 = blockIdx.x;

    // ---- prologue: load+sim tile t0 ----
    if (is_stream) {
        if (t0 < ntiles) {
            uint32_t dstb = (uint32_t)__cvta_generic_to_shared(&sbuf[0]);
            const float4* srcb = (const float4*)hx;
            int base = t0 * TILE_F4;
#pragma unroll
            for (int k = 0; k < TR; k++) {
                int gi = min(base + k * 256 + st, maxf4);
                cp_async16(dstb + (uint32_t)(k * 256 + st) * 16u, srcb + gi);
            }
        }
        cp_commit();
    } else {
        const int trow = warp * 2 + half;
        sim_rows(x, swc, sws, sq, trow,
                 min(t0 * TR + trow, B - 1), lane, lane16);
    }
    __syncthreads();

    int it = 0;
    for (int t = t0; t < ntiles; t += stride, it++) {
        const int tn = t + stride;

        if (is_stream) {
            // ---- issue next tile's loads into the other stage ----
            if (tn < ntiles) {
                uint32_t dstb = (uint32_t)__cvta_generic_to_shared(
                    &sbuf[((it + 1) & 1) * TILE_F4]);
                const float4* srcb = (const float4*)hx;
                int base = tn * TILE_F4;
#pragma unroll
                for (int k = 0; k < TR; k++) {
                    int gi = min(base + k * 256 + st, maxf4);
                    cp_async16(dstb + (uint32_t)(k * 256 + st) * 16u, srcb + gi);
                }
            }
            cp_commit();
            cp_wait1();        // group for tile t complete; tn's stays pending

            // ---- FMA + store tile t ----
            const float4* buf = &sbuf[(it & 1) * TILE_F4];
            const float* sqr = &sq[(it & 1) * (TR * 8)];
            const int row0 = t * TR;
#pragma unroll
            for (int r = 0; r < TR; r++) {
                int b = row0 + r;
                if (b >= B) break;
                float4 qa = *(const float4*)&sqr[r * 8];
                float4 qb = *(const float4*)&sqr[r * 8 + 4];
                float4 v = buf[r * 256 + st];
                float4 acc = bv;
                acc.x += qa.x*w0.x; acc.y += qa.x*w0.y; acc.z += qa.x*w0.z; acc.w += qa.x*w0.w;
                acc.x += qa.y*w1.x; acc.y += qa.y*w1.y; acc.z += qa.y*w1.z; acc.w += qa.y*w1.w;
                acc.x += qa.z*w2.x; acc.y += qa.z*w2.y; acc.z += qa.z*w2.z; acc.w += qa.z*w2.w;
                acc.x += qa.w*w3.x; acc.y += qa.w*w3.y; acc.z += qa.w*w3.z; acc.w += qa.w*w3.w;
                acc.x += qb.x*w4.x; acc.y += qb.x*w4.y; acc.z += qb.x*w4.z; acc.w += qb.x*w4.w;
                acc.x += qb.y*w5.x; acc.y += qb.y*w5.y; acc.z += qb.y*w5.z; acc.w += qb.y*w5.w;
                v.x += acc.x; v.y += acc.y; v.z += acc.z; v.w += acc.w;
                __stcs((float4*)(out + (size_t)b * HDIM) + st, v);
            }
        } else {
            // ---- sim next tile into the other sq buffer ----
            if (tn < ntiles) {
                const int trow = warp * 2 + half;
                sim_rows(x, swc, sws, &sq[((it + 1) & 1) * (TR * 8)], trow,
                         min(tn * TR + trow, B - 1), lane, lane16);
            }
        }
        __syncthreads();       // sq/stage handoff for next iteration
    }
}

// ---- launch ----------------------------------------------------------------
extern "C" void kernel_launch(void* const* d_in, const int* in_sizes, int n_in,
                              void* d_out, int out_size) {
    const float* x    = (const float*)d_in[0];   // (B,6)
    const float* hx   = (const float*)d_in[1];   // (B,1024)
    const float* qw   = (const float*)d_in[2];   // (3,6)
    const float* fc_w = (const float*)d_in[3];   // (1024,6)
    const float* fc_b = (const float*)d_in[4];   // (1024,)
    float* out = (float*)d_out;

    int B = in_sizes[0] / NQ;
    int ntiles = (B + TR - 1) / TR;

    const int smem_bytes = STAGES * TILE_F4 * 16 + 2 * TR * 8 * 4
                         + 2 * NLAYERS * NQ * 4;

    cudaFuncSetAttribute(fused_kernel,
                         cudaFuncAttributeMaxDynamicSharedMemorySize,
                         smem_bytes);

    int grid = 148 * 2;
    if (grid > ntiles) grid = ntiles;
    fused_kernel<<<grid, NTHREADS, smem_bytes>>>(x, hx, qw, fc_w, fc_b, out,
                                                 B, ntiles);
}